// round 1
// baseline (speedup 1.0000x reference)
#include <cuda_runtime.h>
#include <cuda_bf16.h>
#include <math.h>

// out[d, l] (row-major, D x L):
//   l == 0   : h_0[d]
//   l >= 1   : sum_k Re( R[k,d] * p[k,d]^(l-1) ),  p = r * exp(i*theta)
//
// Per (k,d): a_t = Re(R p^t) obeys a_t = (2 r cos(theta)) a_{t-1} - r^2 a_{t-2}.
// Thread = (one d, one chunk of C consecutive l). 3 flops per (k,t).

#define CHUNK 64
#define TD    64   // d's per block (= threads per block)

__global__ __launch_bounds__(TD) void lh_modal_kernel(
    const float* __restrict__ rr,
    const float* __restrict__ th,
    const float* __restrict__ Rre,
    const float* __restrict__ Rim,
    const float* __restrict__ h0,
    float* __restrict__ out,
    int D, int L, int K)
{
    const int l0 = blockIdx.x * CHUNK;
    const int d0 = blockIdx.y * TD;
    const int tid = threadIdx.x;
    const int d = d0 + tid;

    __shared__ float tile[TD][CHUNK + 1];   // +1 pad: conflict-free transpose

    float acc[CHUNK];
#pragma unroll
    for (int i = 0; i < CHUNK; ++i) acc[i] = 0.0f;

    // Seeds are computed at t0 = l0 - 1 (a_t with t = l-1). For l0==0 this is
    // t0 = -1, which is fine (r >= 0.4); acc[0] is overwritten with h_0 below.
    const int t0 = l0 - 1;
    const float t0f = (float)t0;
    const double t0d = (double)t0;
    const double INV2PI = 0.15915494309189534840;
    const double TWO_PI = 6.28318530717958647692;

    for (int k = 0; k < K; ++k) {
        const int idx = k * D + d;
        const float r  = rr[idx];
        const float t_ = th[idx];
        const float Ar = Rre[idx];
        const float Ai = Rim[idx];

        float st, ct;
        sincosf(t_, &st, &ct);
        const float pre1 = r * ct;          // Re(p)
        const float pim1 = r * st;          // Im(p)
        const float c1 = 2.0f * pre1;       // recurrence coeffs
        const float c2 = r * r;

        // p^{t0} = rho * (cos phi, sin phi); phase reduced in fp64 for accuracy
        const float rho = expf(t0f * logf(r));
        double ph = t0d * (double)t_;
        double q = rint(ph * INV2PI);
        float phi = (float)(ph - q * TWO_PI);
        float sp, cp;
        sincosf(phi, &sp, &cp);
        const float pre = rho * cp;
        const float pim = rho * sp;

        // a0 = Re(R p^{t0}),  a1 = Re(R p^{t0+1})
        float a0 = fmaf(Ar, pre, -Ai * pim);
        float wim = fmaf(Ar, pim,  Ai * pre);
        float a1 = fmaf(a0, pre1, -wim * pim1);

        acc[0] += a0;
        acc[1] += a1;
#pragma unroll
        for (int i = 2; i < CHUNK; ++i) {
            float m  = -c2 * a0;            // off the 4-cycle FMA chain
            float a2 = fmaf(c1, a1, m);     // critical path: 1 FMA / step
            acc[i] += a2;
            a0 = a1;
            a1 = a2;
        }
    }

    if (l0 == 0) acc[0] = h0[d];

    // Transpose through shared so global stores are coalesced.
#pragma unroll
    for (int i = 0; i < CHUNK; ++i) tile[tid][i] = acc[i];
    __syncthreads();

    const int total = TD * CHUNK;
    for (int j = tid; j < total; j += TD) {
        int row = j >> 6;          // / CHUNK
        int col = j & (CHUNK - 1); // % CHUNK
        int l = l0 + col;
        if (l < L) out[(size_t)(d0 + row) * L + l] = tile[row][col];
    }
}

extern "C" void kernel_launch(void* const* d_in, const int* in_sizes, int n_in,
                              void* d_out, int out_size)
{
    const float* rr  = (const float*)d_in[0];
    const float* th  = (const float*)d_in[1];
    const float* Rre = (const float*)d_in[2];
    const float* Rim = (const float*)d_in[3];
    const float* h0  = (const float*)d_in[4];
    float* out = (float*)d_out;

    const int D = in_sizes[4];                  // h_0 has D elements
    const int K = in_sizes[0] / D;              // r is (K, D)
    const int L = out_size / D;

    dim3 block(TD);
    dim3 grid((L + CHUNK - 1) / CHUNK, D / TD);
    lh_modal_kernel<<<grid, block>>>(rr, th, Rre, Rim, h0, out, D, L, K);
}

// round 2
// speedup vs baseline: 1.1954x; 1.1954x over previous
#include <cuda_runtime.h>
#include <cuda_bf16.h>
#include <math.h>

// out[d, l] (row-major, D x L):
//   l == 0 : h_0[d];  l >= 1 : sum_k Re( R[k,d] * p[k,d]^(l-1) )
// Recurrence per (k,d): a_t = (2 r cosT) a_{t-1} - r^2 a_{t-2}
// This version: 4 k-chains in flight per thread, packed 2-wide into f32x2
// registers (FFMA2 path). 6 packed fma-class ops advance 4 (k,t) elements.

#define CHUNK 64
#define TD    32    // one warp per block; D-tile = 32

typedef unsigned long long u64p;   // carrier for packed f32x2

__device__ __forceinline__ u64p pk2(float lo, float hi) {
    u64p r; asm("mov.b64 %0, {%1, %2};" : "=l"(r) : "f"(lo), "f"(hi)); return r;
}
__device__ __forceinline__ void upk2(u64p v, float& lo, float& hi) {
    asm("mov.b64 {%0, %1}, %2;" : "=f"(lo), "=f"(hi) : "l"(v));
}
__device__ __forceinline__ u64p mul2(u64p a, u64p b) {
    u64p r; asm("mul.rn.f32x2 %0, %1, %2;" : "=l"(r) : "l"(a), "l"(b)); return r;
}
__device__ __forceinline__ u64p add2(u64p a, u64p b) {
    u64p r; asm("add.rn.f32x2 %0, %1, %2;" : "=l"(r) : "l"(a), "l"(b)); return r;
}
__device__ __forceinline__ u64p fma2(u64p a, u64p b, u64p c) {
    u64p r; asm("fma.rn.f32x2 %0, %1, %2, %3;" : "=l"(r) : "l"(a), "l"(b), "l"(c)); return r;
}

__global__ __launch_bounds__(TD) void lh_modal_kernel(
    const float* __restrict__ rr,
    const float* __restrict__ th,
    const float* __restrict__ Rre,
    const float* __restrict__ Rim,
    const float* __restrict__ h0,
    float* __restrict__ out,
    int D, int L, int K)
{
    const int l0 = blockIdx.x * CHUNK;
    const int d0 = blockIdx.y * TD;
    const int tid = threadIdx.x;
    const int d = d0 + tid;

    __shared__ float tile[TD][CHUNK + 1];

    u64p acc[CHUNK];
    const u64p z = pk2(0.0f, 0.0f);
#pragma unroll
    for (int i = 0; i < CHUNK; ++i) acc[i] = z;

    const int t0 = l0 - 1;             // a_t uses t = l-1; t0=-1 ok (r>=0.4)
    const float t0f = (float)t0;
    const double t0d = (double)t0;
    const double INV2PI = 0.15915494309189534840;
    const double TWO_PI = 6.28318530717958647692;

    for (int kg = 0; kg < K; kg += 4) {
        // ---- scalar seed/coeff setup for 4 poles ----
        float sa0[4], sa1[4], sc1[4], sc2[4];
#pragma unroll
        for (int u = 0; u < 4; ++u) {
            const int idx = (kg + u) * D + d;
            const float r  = rr[idx];
            const float t_ = th[idx];
            const float Ar = Rre[idx];
            const float Ai = Rim[idx];

            float st, ct;
            sincosf(t_, &st, &ct);
            const float pre1 = r * ct;
            const float pim1 = r * st;
            sc1[u] = 2.0f * pre1;
            sc2[u] = r * r;

            // p^{t0}: magnitude via exp/log, phase reduced mod 2pi in fp64
            const float rho = expf(t0f * logf(r));
            double ph = t0d * (double)t_;
            double q = rint(ph * INV2PI);
            float phi = (float)(ph - q * TWO_PI);
            float sp, cp;
            sincosf(phi, &sp, &cp);
            const float pre = rho * cp;
            const float pim = rho * sp;

            float a0 = fmaf(Ar, pre, -Ai * pim);          // Re(R p^{t0})
            float wi = fmaf(Ar, pim,  Ai * pre);          // Im(R p^{t0})
            sa0[u] = a0;
            sa1[u] = fmaf(a0, pre1, -wi * pim1);          // Re(R p^{t0+1})
        }

        // ---- pack into two 2-wide chains ----
        u64p A0_0 = pk2(sa0[0], sa0[1]);
        u64p A0_1 = pk2(sa0[2], sa0[3]);
        u64p A1_0 = pk2(sa1[0], sa1[1]);
        u64p A1_1 = pk2(sa1[2], sa1[3]);
        u64p C1_0 = pk2(sc1[0], sc1[1]);
        u64p C1_1 = pk2(sc1[2], sc1[3]);
        u64p nC2_0 = pk2(-sc2[0], -sc2[1]);
        u64p nC2_1 = pk2(-sc2[2], -sc2[3]);

        acc[0] = add2(acc[0], add2(A0_0, A0_1));
        acc[1] = add2(acc[1], add2(A1_0, A1_1));

#pragma unroll
        for (int i = 2; i < CHUNK; ++i) {
            u64p m0 = mul2(nC2_0, A0_0);        // off chain
            u64p m1 = mul2(nC2_1, A0_1);
            u64p n0 = fma2(C1_0, A1_0, m0);     // chain step (lat 4, 6 instrs apart)
            u64p n1 = fma2(C1_1, A1_1, m1);
            acc[i] = add2(acc[i], add2(n0, n1));
            A0_0 = A1_0; A1_0 = n0;
            A0_1 = A1_1; A1_1 = n1;
        }
    }

    // ---- reduce packed halves, patch h0, transpose, store ----
#pragma unroll
    for (int i = 0; i < CHUNK; ++i) {
        float lo, hi;
        upk2(acc[i], lo, hi);
        tile[tid][i] = lo + hi;
    }
    if (l0 == 0) tile[tid][0] = h0[d];
    __syncthreads();

    const int total = TD * CHUNK;
    for (int j = tid; j < total; j += TD) {
        int row = j >> 6;            // / CHUNK
        int col = j & (CHUNK - 1);   // % CHUNK
        int l = l0 + col;
        if (l < L) out[(size_t)(d0 + row) * L + l] = tile[row][col];
    }
}

extern "C" void kernel_launch(void* const* d_in, const int* in_sizes, int n_in,
                              void* d_out, int out_size)
{
    const float* rr  = (const float*)d_in[0];
    const float* th  = (const float*)d_in[1];
    const float* Rre = (const float*)d_in[2];
    const float* Rim = (const float*)d_in[3];
    const float* h0  = (const float*)d_in[4];
    float* out = (float*)d_out;

    const int D = in_sizes[4];
    const int K = in_sizes[0] / D;
    const int L = out_size / D;

    dim3 block(TD);
    dim3 grid((L + CHUNK - 1) / CHUNK, D / TD);
    lh_modal_kernel<<<grid, block>>>(rr, th, Rre, Rim, h0, out, D, L, K);
}

// round 3
// speedup vs baseline: 1.5104x; 1.2635x over previous
#include <cuda_runtime.h>
#include <cuda_bf16.h>
#include <math.h>

// out[d,l]: l==0 -> h0[d]; l>=1 -> sum_k Re(R[k,d] * p[k,d]^(l-1)).
// Recurrence a_t = c1*a_{t-1} - r^2*a_{t-2}, c1 = 2 r cos(theta).
// Kernel A seeds each 64-long l-chunk via p^64 powers (no fp64, 1 sincos/pole).
// Kernel B runs the packed f32x2 recurrence (pure FMA).

#define CHUNK 64
#define MAXD  1024
#define MAXK  32
#define MAXBX 64          // max l-chunks supported (L <= 4096)

__device__ float  g_c1 [MAXK * MAXD];
__device__ float  g_nc2[MAXK * MAXD];
__device__ float2 g_seed[MAXBX * MAXK * MAXD];   // (a0, a1) per (bx, k, d)

typedef unsigned long long u64p;

__device__ __forceinline__ u64p pk2(float lo, float hi) {
    u64p r; asm("mov.b64 %0, {%1, %2};" : "=l"(r) : "f"(lo), "f"(hi)); return r;
}
__device__ __forceinline__ void upk2(u64p v, float& lo, float& hi) {
    asm("mov.b64 {%0, %1}, %2;" : "=f"(lo), "=f"(hi) : "l"(v));
}
__device__ __forceinline__ u64p mul2(u64p a, u64p b) {
    u64p r; asm("mul.rn.f32x2 %0, %1, %2;" : "=l"(r) : "l"(a), "l"(b)); return r;
}
__device__ __forceinline__ u64p add2(u64p a, u64p b) {
    u64p r; asm("add.rn.f32x2 %0, %1, %2;" : "=l"(r) : "l"(a), "l"(b)); return r;
}
__device__ __forceinline__ u64p fma2(u64p a, u64p b, u64p c) {
    u64p r; asm("fma.rn.f32x2 %0, %1, %2, %3;" : "=l"(r) : "l"(a), "l"(b), "l"(c)); return r;
}

// ---------------- Kernel A: seeds ----------------
__global__ void lh_seed_kernel(
    const float* __restrict__ rr, const float* __restrict__ th,
    const float* __restrict__ Rre, const float* __restrict__ Rim,
    int D, int K, int NBX)
{
    const int i = blockIdx.x * blockDim.x + threadIdx.x;   // i = k*D + d
    if (i >= K * D) return;

    const float r  = rr[i];
    const float t_ = th[i];
    const float Ar = Rre[i];
    const float Ai = Rim[i];

    float st, ct;
    sincosf(t_, &st, &ct);
    const float pre = r * ct;        // Re(p)
    const float pim = r * st;        // Im(p)

    g_c1 [i] = 2.0f * pre;
    g_nc2[i] = -(r * r);
    const float invr2 = 1.0f / (r * r);

    // p^64 via 6 complex squarings
    float wr = pre, wi = pim;
#pragma unroll
    for (int s = 0; s < 6; ++s) {
        float nr = fmaf(wr, wr, -wi * wi);
        float ni = 2.0f * wr * wi;
        wr = nr; wi = ni;
    }
    const float p64r = wr, p64i = wi;

    // march w = p^(64*bx); emit a1 = Re(R w)  (t = 64bx),
    //                        a0 = Re(R w conj(p))/r^2  (t = 64bx - 1)
    float cr = 1.0f, ci = 0.0f;
    for (int bx = 0; bx < NBX; ++bx) {
        float zr = fmaf(Ar, cr, -Ai * ci);   // Re(R w)
        float zi = fmaf(Ar, ci,  Ai * cr);   // Im(R w)
        float a1 = zr;
        float a0 = fmaf(zr, pre, zi * pim) * invr2;
        g_seed[(size_t)bx * K * D + i] = make_float2(a0, a1);

        float nr = fmaf(cr, p64r, -ci * p64i);
        float ni = fmaf(cr, p64i,  ci * p64r);
        cr = nr; ci = ni;
    }
}

// ---------------- Kernel B: recurrence ----------------
// Block: 64 threads = 2 warps. d-tile = 32 (lane), l-chunk = 64 (blockIdx.x).
// Warp w handles k in [w*K/2, (w+1)*K/2), groups of 4 poles -> 2 packed chains.
__global__ __launch_bounds__(64) void lh_recur_kernel(
    const float* __restrict__ h0, float* __restrict__ out,
    int D, int L, int K)
{
    const int bx   = blockIdx.x;          // l-chunk index
    const int l0   = bx * CHUNK;
    const int d0   = blockIdx.y * 32;
    const int lane = threadIdx.x & 31;
    const int wid  = threadIdx.x >> 5;
    const int d    = d0 + lane;

    __shared__ float tile[2][32][CHUNK + 1];

    u64p acc[CHUNK];
    const u64p z = pk2(0.0f, 0.0f);
#pragma unroll
    for (int i = 0; i < CHUNK; ++i) acc[i] = z;

    const int kbeg = wid * (K >> 1);
    const int kend = kbeg + (K >> 1);
    const float2* __restrict__ seed = &g_seed[(size_t)bx * K * D];

    for (int kg = kbeg; kg < kend; kg += 4) {
        float sc1[4], sn2[4], sa0[4], sa1[4];
#pragma unroll
        for (int u = 0; u < 4; ++u) {
            const int idx = (kg + u) * D + d;
            sc1[u] = g_c1[idx];
            sn2[u] = g_nc2[idx];
            float2 s = seed[idx];
            sa0[u] = s.x; sa1[u] = s.y;
        }

        u64p A0_0 = pk2(sa0[0], sa0[1]);
        u64p A0_1 = pk2(sa0[2], sa0[3]);
        u64p A1_0 = pk2(sa1[0], sa1[1]);
        u64p A1_1 = pk2(sa1[2], sa1[3]);
        u64p C1_0 = pk2(sc1[0], sc1[1]);
        u64p C1_1 = pk2(sc1[2], sc1[3]);
        u64p N2_0 = pk2(sn2[0], sn2[1]);
        u64p N2_1 = pk2(sn2[2], sn2[3]);

        acc[0] = add2(acc[0], add2(A0_0, A0_1));
        acc[1] = add2(acc[1], add2(A1_0, A1_1));

#pragma unroll
        for (int i = 2; i < CHUNK; ++i) {
            u64p m0 = mul2(N2_0, A0_0);
            u64p m1 = mul2(N2_1, A0_1);
            u64p n0 = fma2(C1_0, A1_0, m0);
            u64p n1 = fma2(C1_1, A1_1, m1);
            acc[i] = add2(acc[i], add2(n0, n1));
            A0_0 = A1_0; A1_0 = n0;
            A0_1 = A1_1; A1_1 = n1;
        }
    }

#pragma unroll
    for (int i = 0; i < CHUNK; ++i) {
        float lo, hi;
        upk2(acc[i], lo, hi);
        tile[wid][lane][i] = lo + hi;
    }
    __syncthreads();

    // combine warps, patch h0, coalesced store
    const int total = 32 * CHUNK;
    for (int j = threadIdx.x; j < total; j += 64) {
        int row = j >> 6;
        int col = j & (CHUNK - 1);
        int l = l0 + col;
        float v = tile[0][row][col] + tile[1][row][col];
        if (l0 == 0 && col == 0) v = h0[d0 + row];
        if (l < L) out[(size_t)(d0 + row) * L + l] = v;
    }
}

extern "C" void kernel_launch(void* const* d_in, const int* in_sizes, int n_in,
                              void* d_out, int out_size)
{
    const float* rr  = (const float*)d_in[0];
    const float* th  = (const float*)d_in[1];
    const float* Rre = (const float*)d_in[2];
    const float* Rim = (const float*)d_in[3];
    const float* h0  = (const float*)d_in[4];
    float* out = (float*)d_out;

    const int D = in_sizes[4];
    const int K = in_sizes[0] / D;
    const int L = out_size / D;
    const int NBX = (L + CHUNK - 1) / CHUNK;

    const int na = K * D;
    lh_seed_kernel<<<(na + 255) / 256, 256>>>(rr, th, Rre, Rim, D, K, NBX);

    dim3 grid(NBX, D / 32);
    lh_recur_kernel<<<grid, 64>>>(h0, out, D, L, K);
}

// round 4
// speedup vs baseline: 1.6626x; 1.1008x over previous
#include <cuda_runtime.h>
#include <cuda_bf16.h>
#include <math.h>

// out[d,l]: l==0 -> h0[d]; l>=1 -> sum_k Re(R[k,d]*p[k,d]^(l-1))
// a_t = c1*a_{t-1} - r^2*a_{t-2}; c1 = 2 r cos(theta).
// Kernel A: per-(pole, 8-chunk segment) seeding, no fp64, 1 sincos/pole-seg.
// Kernel B: packed f32x2 recurrence, software-pipelined accumulate.

#define CHUNK 32
#define MAXD  1024
#define MAXK  32
#define MAXBX 128          // supports L <= 4096
#define SEGC  8            // chunks per seed thread

__device__ float  g_c1 [MAXK * MAXD];
__device__ float  g_nc2[MAXK * MAXD];
__device__ float2 g_seed[MAXBX * MAXK * MAXD];   // (a0, a1) per (bx, k, d)

typedef unsigned long long u64p;

__device__ __forceinline__ u64p pk2(float lo, float hi) {
    u64p r; asm("mov.b64 %0, {%1, %2};" : "=l"(r) : "f"(lo), "f"(hi)); return r;
}
__device__ __forceinline__ void upk2(u64p v, float& lo, float& hi) {
    asm("mov.b64 {%0, %1}, %2;" : "=f"(lo), "=f"(hi) : "l"(v));
}
__device__ __forceinline__ u64p mul2(u64p a, u64p b) {
    u64p r; asm("mul.rn.f32x2 %0, %1, %2;" : "=l"(r) : "l"(a), "l"(b)); return r;
}
__device__ __forceinline__ u64p add2(u64p a, u64p b) {
    u64p r; asm("add.rn.f32x2 %0, %1, %2;" : "=l"(r) : "l"(a), "l"(b)); return r;
}
__device__ __forceinline__ u64p fma2(u64p a, u64p b, u64p c) {
    u64p r; asm("fma.rn.f32x2 %0, %1, %2, %3;" : "=l"(r) : "l"(a), "l"(b), "l"(c)); return r;
}

// ---------------- Kernel A: seeds (parallel over 8-chunk segments) ----------
__global__ void lh_seed_kernel(
    const float* __restrict__ rr, const float* __restrict__ th,
    const float* __restrict__ Rre, const float* __restrict__ Rim,
    int D, int K, int NBX)
{
    const int KD = K * D;
    const int gi = blockIdx.x * blockDim.x + threadIdx.x;
    const int nseg = (NBX + SEGC - 1) / SEGC;
    if (gi >= KD * nseg) return;
    const int i   = gi % KD;      // pole index k*D + d (coalesced)
    const int seg = gi / KD;

    const float r  = rr[i];
    const float t_ = th[i];
    const float Ar = Rre[i];
    const float Ai = Rim[i];

    float st, ct;
    sincosf(t_, &st, &ct);
    const float pre = r * ct;      // Re(p)
    const float pim = r * st;      // Im(p)

    if (seg == 0) {
        g_c1 [i] = 2.0f * pre;
        g_nc2[i] = -(r * r);
    }
    const float invr2 = 1.0f / (r * r);

    // q = p^CHUNK (5 squarings for CHUNK=32)
    float qr = pre, qi = pim;
#pragma unroll
    for (int s = 0; s < 5; ++s) {
        float nr = fmaf(qr, qr, -qi * qi);
        float ni = 2.0f * qr * qi;
        qr = nr; qi = ni;
    }
    // q8 = q^SEGC = p^(CHUNK*SEGC)  (3 squarings for SEGC=8)
    float q8r = qr, q8i = qi;
#pragma unroll
    for (int s = 0; s < 3; ++s) {
        float nr = fmaf(q8r, q8r, -q8i * q8i);
        float ni = 2.0f * q8r * q8i;
        q8r = nr; q8i = ni;
    }
    // w = q8^seg, seg in [0,7], binary powering
    float wr = 1.0f, wi = 0.0f;
    {
        float br = q8r, bi = q8i;
        int e = seg;
#pragma unroll
        for (int b = 0; b < 3; ++b) {
            if (e & 1) {
                float nr = fmaf(wr, br, -wi * bi);
                float ni = fmaf(wr, bi,  wi * br);
                wr = nr; wi = ni;
            }
            e >>= 1;
            float sr = fmaf(br, br, -bi * bi);
            float si = 2.0f * br * bi;
            br = sr; bi = si;
        }
    }

    // emit seeds for chunks bx = seg*SEGC + j;  w = p^(CHUNK*bx)
#pragma unroll
    for (int j = 0; j < SEGC; ++j) {
        int bx = seg * SEGC + j;
        if (bx < NBX) {
            float zr = fmaf(Ar, wr, -Ai * wi);   // Re(R w) = a(CHUNK*bx)
            float zi = fmaf(Ar, wi,  Ai * wr);   // Im(R w)
            float a1 = zr;
            float a0 = fmaf(zr, pre, zi * pim) * invr2;  // a(CHUNK*bx - 1)
            g_seed[(size_t)bx * KD + i] = make_float2(a0, a1);
        }
        float nr = fmaf(wr, qr, -wi * qi);
        float ni = fmaf(wr, qi,  wi * qr);
        wr = nr; wi = ni;
    }
}

// ---------------- Kernel B: recurrence ----------------
// Block 64 thr = 2 warps; d-tile 32 (lane); l-chunk 32 (blockIdx.x).
// Warp w: k in [w*K/2, (w+1)*K/2), groups of 4 -> two packed chains.
__global__ __launch_bounds__(64, 8) void lh_recur_kernel(
    const float* __restrict__ h0, float* __restrict__ out,
    int D, int L, int K)
{
    const int bx   = blockIdx.x;
    const int l0   = bx * CHUNK;
    const int d0   = blockIdx.y * 32;
    const int lane = threadIdx.x & 31;
    const int wid  = threadIdx.x >> 5;
    const int d    = d0 + lane;
    const int KD   = K * D;

    __shared__ float tile[2][32][CHUNK + 1];

    u64p acc[CHUNK];
    const u64p z = pk2(0.0f, 0.0f);
#pragma unroll
    for (int i = 0; i < CHUNK; ++i) acc[i] = z;

    const int kbeg = wid * (K >> 1);
    const int kend = kbeg + (K >> 1);
    const float2* __restrict__ seed = &g_seed[(size_t)bx * KD];

    for (int kg = kbeg; kg < kend; kg += 4) {
        float sc1[4], sn2[4], sa0[4], sa1[4];
#pragma unroll
        for (int u = 0; u < 4; ++u) {
            const int idx = (kg + u) * D + d;
            sc1[u] = g_c1[idx];
            sn2[u] = g_nc2[idx];
            float2 s = seed[idx];
            sa0[u] = s.x; sa1[u] = s.y;
        }

        u64p A0_0 = pk2(sa0[0], sa0[1]);
        u64p A0_1 = pk2(sa0[2], sa0[3]);
        u64p A1_0 = pk2(sa1[0], sa1[1]);
        u64p A1_1 = pk2(sa1[2], sa1[3]);
        u64p C1_0 = pk2(sc1[0], sc1[1]);
        u64p C1_1 = pk2(sc1[2], sc1[3]);
        u64p N2_0 = pk2(sn2[0], sn2[1]);
        u64p N2_1 = pk2(sn2[2], sn2[3]);

        acc[0] = add2(acc[0], add2(A0_0, A0_1));
        acc[1] = add2(acc[1], add2(A1_0, A1_1));

        // software-pipelined: pair-sum S lands in acc one iteration late,
        // so every consumer is >= 2 issues from its producer (no stalls).
        u64p S = z;
#pragma unroll
        for (int i = 2; i < CHUNK; ++i) {
            u64p m0 = mul2(N2_0, A0_0);
            u64p m1 = mul2(N2_1, A0_1);
            u64p n0 = fma2(C1_0, A1_0, m0);
            u64p n1 = fma2(C1_1, A1_1, m1);
            if (i > 2) acc[i - 1] = add2(acc[i - 1], S);
            S = add2(n0, n1);
            A0_0 = A1_0; A1_0 = n0;
            A0_1 = A1_1; A1_1 = n1;
        }
        acc[CHUNK - 1] = add2(acc[CHUNK - 1], S);
    }

#pragma unroll
    for (int i = 0; i < CHUNK; ++i) {
        float lo, hi;
        upk2(acc[i], lo, hi);
        tile[wid][lane][i] = lo + hi;
    }
    __syncthreads();

    const int total = 32 * CHUNK;
    for (int j = threadIdx.x; j < total; j += 64) {
        int row = j >> 5;            // / CHUNK
        int col = j & (CHUNK - 1);   // % CHUNK
        int l = l0 + col;
        float v = tile[0][row][col] + tile[1][row][col];
        if (l0 == 0 && col == 0) v = h0[d0 + row];
        if (l < L) out[(size_t)(d0 + row) * L + l] = v;
    }
}

extern "C" void kernel_launch(void* const* d_in, const int* in_sizes, int n_in,
                              void* d_out, int out_size)
{
    const float* rr  = (const float*)d_in[0];
    const float* th  = (const float*)d_in[1];
    const float* Rre = (const float*)d_in[2];
    const float* Rim = (const float*)d_in[3];
    const float* h0  = (const float*)d_in[4];
    float* out = (float*)d_out;

    const int D = in_sizes[4];
    const int K = in_sizes[0] / D;
    const int L = out_size / D;
    const int NBX = (L + CHUNK - 1) / CHUNK;
    const int nseg = (NBX + SEGC - 1) / SEGC;

    const int na = K * D * nseg;
    lh_seed_kernel<<<(na + 255) / 256, 256>>>(rr, th, Rre, Rim, D, K, NBX);

    dim3 grid(NBX, D / 32);
    lh_recur_kernel<<<grid, 64>>>(h0, out, D, L, K);
}